// round 4
// baseline (speedup 1.0000x reference)
#include <cuda_runtime.h>
#include <math.h>

#define NDIM 768
#define FDIM 128
#define HDIM 128
#define NN (NDIM*NDIM)
#define EUP ((NDIM*(NDIM-1))/2)   // 294528 upper-triangle edges per batch

// scratch (no cudaMalloc allowed)
__device__ float g_Xc[2*2*NDIM*64];   // [b][ch][i][d]
__device__ float g_P[2*2*NN];         // [b][ch][i][j]  (only i<j tiles valid)

// packed 2xfp32 FMA (sm_100+); bit-identical to two scalar fmaf (RN)
union F2U { float2 f; unsigned long long u; };
__device__ __forceinline__ float2 ffma2(float2 a, float2 b, float2 c) {
    F2U A, B, C, D;
    A.f = a; B.f = b; C.f = c;
    asm("fma.rn.f32x2 %0, %1, %2, %3;" : "=l"(D.u) : "l"(A.u), "l"(B.u), "l"(C.u));
    return D.f;
}

__device__ __forceinline__ void cpa16(void* dst_smem, const void* src) {
    unsigned sa = (unsigned)__cvta_generic_to_shared(dst_smem);
    asm volatile("cp.async.cg.shared.global [%0], [%1], 16;\n" :: "r"(sa), "l"(src));
}
#define CP_COMMIT() asm volatile("cp.async.commit_group;\n" ::: "memory")
#define CP_WAIT(n)  asm volatile("cp.async.wait_group %0;\n" :: "n"(n) : "memory")

// ---------------------------------------------------------------------------
// K1: Xc = Xskip + gate * (relu(X@W1+b1)@W2+b2)
// 384 blocks x 256 threads, 4 rows/block. Weights staged GMEM->SMEM with
// cp.async double-buffered 32-f chunks so global latency never touches the
// compute loop. Thread (h = t&127, s = t>>7) owns rows {2s, 2s+1} at output
// column h -> one fma.f32x2 per f.
// ---------------------------------------------------------------------------
#define PR_ROWS  4
#define PR_CHUNK 32
#define PR_NCH   (FDIM / PR_CHUNK)   // 4

struct PrepSmem {
    __align__(16) float xs[FDIM][PR_ROWS];              // 2KB  [f][r]
    __align__(16) float hs[HDIM][PR_ROWS];              // 2KB  [h][r]
    __align__(16) float ws[2][PR_CHUNK][HDIM];          // 32KB double-buffered weights
};

__device__ __forceinline__ float2 prep_layer(
    const float* __restrict__ W, float bias,
    const float (*in)[PR_ROWS], float ws[2][PR_CHUNK][HDIM], int t)
{
    const int h = t & 127;
    const int s = t >> 7;
    float2 acc = make_float2(bias, bias);

    // prologue: chunk 0  (16KB = 1024 x 16B; 256 threads x 4)
    {
        float* dst = &ws[0][0][0];
        #pragma unroll
        for (int it = 0; it < 4; it++) {
            const int idx = (it * 256 + t) * 4;
            cpa16(dst + idx, W + idx);
        }
        CP_COMMIT();
    }

    #pragma unroll
    for (int c = 0; c < PR_NCH; c++) {
        const int buf = c & 1;
        if (c + 1 < PR_NCH) {
            const float* src = W + (size_t)(c + 1) * PR_CHUNK * HDIM;
            float* dst = &ws[(c + 1) & 1][0][0];
            #pragma unroll
            for (int it = 0; it < 4; it++) {
                const int idx = (it * 256 + t) * 4;
                cpa16(dst + idx, src + idx);
            }
            CP_COMMIT();
            CP_WAIT(1);
        } else {
            CP_WAIT(0);
        }
        __syncthreads();   // chunk c visible to all

        #pragma unroll
        for (int fi = 0; fi < PR_CHUNK; fi++) {
            const int f = c * PR_CHUNK + fi;
            const float w = ws[buf][fi][h];
            const float2 xv = *(const float2*)&in[f][2 * s];
            acc = ffma2(xv, make_float2(w, w), acc);
        }
        __syncthreads();   // protect buf before it is refilled
    }
    return acc;
}

__global__ __launch_bounds__(256) void k_prep(
    const float* __restrict__ X,
    const float* __restrict__ w1, const float* __restrict__ b1,
    const float* __restrict__ w2, const float* __restrict__ b2,
    const float* __restrict__ gate)
{
    __shared__ PrepSmem sm;
    const int t = threadIdx.x;
    const int h = t & 127;
    const int s = t >> 7;
    const int row0 = blockIdx.x * PR_ROWS;   // 768 % 4 == 0 -> no batch straddle
    const float g = gate[0];

    // stage X rows: thread t loads col (t&127) of rows {2*(t>>7), +1}
    {
        const int f = t & 127;
        const int r0 = (t >> 7) * 2;
        sm.xs[f][r0]     = X[(size_t)(row0 + r0) * FDIM + f];
        sm.xs[f][r0 + 1] = X[(size_t)(row0 + r0 + 1) * FDIM + f];
    }
    // (first __syncthreads inside prep_layer covers xs visibility)

    // layer 1 + relu
    float2 a1 = prep_layer(w1, b1[h], sm.xs, sm.ws, t);
    sm.hs[h][2 * s]     = fmaxf(a1.x, 0.0f);
    sm.hs[h][2 * s + 1] = fmaxf(a1.y, 0.0f);
    __syncthreads();

    // layer 2
    float2 a2 = prep_layer(w2, b2[h], sm.hs, sm.ws, t);

    // Xc = Xskip + g * act
    const int b  = row0 / NDIM;
    const int ch = h & 1;
    const int d  = h >> 1;
    const int i0 = (row0 % NDIM) + 2 * s;
    float* dst = g_Xc + ((size_t)(b * 2 + ch) * NDIM + i0) * 64 + d;
    dst[0]  = sm.xs[h][2 * s]     + g * a2.x;
    dst[64] = sm.xs[h][2 * s + 1] + g * a2.y;
}

// ---------------------------------------------------------------------------
// K2: gram  P[bc][i][j] = sum_d Xc[bc][i][d]*Xc[bc][j][d]
// 64x64 tiles, upper triangle only; f32x2-packed along j
// ---------------------------------------------------------------------------
__global__ __launch_bounds__(256) void k_gram()
{
    __shared__ float As[64][68];   // [d][row i]
    __shared__ float Bs[64][68];   // [d][row j]
    const int tid = threadIdx.x;
    const int bc  = blockIdx.y;    // b*2+ch

    int bi = 0, rem = blockIdx.x;
    while (rem >= 12 - bi) { rem -= 12 - bi; bi++; }
    const int bj = bi + rem;

    const float* Xbase = g_Xc + (size_t)bc * NDIM * 64;
    for (int idx = tid; idx < 4096; idx += 256) {
        const int r = idx >> 6, d = idx & 63;
        As[d][r] = Xbase[(bi * 64 + r) * 64 + d];
        Bs[d][r] = Xbase[(bj * 64 + r) * 64 + d];
    }
    __syncthreads();

    const int tx = tid & 15, ty = tid >> 4;
    float2 c2[4][2];
    #pragma unroll
    for (int a = 0; a < 4; a++) {
        c2[a][0] = make_float2(0.0f, 0.0f);
        c2[a][1] = make_float2(0.0f, 0.0f);
    }

    #pragma unroll 8
    for (int d = 0; d < 64; d++) {
        const float4 av = *(const float4*)&As[d][ty * 4];
        const float4 bv = *(const float4*)&Bs[d][tx * 4];
        const float2 b01 = make_float2(bv.x, bv.y);
        const float2 b23 = make_float2(bv.z, bv.w);
        const float aa[4] = {av.x, av.y, av.z, av.w};
        #pragma unroll
        for (int a = 0; a < 4; a++) {
            const float2 a2 = make_float2(aa[a], aa[a]);
            c2[a][0] = ffma2(a2, b01, c2[a][0]);
            c2[a][1] = ffma2(a2, b23, c2[a][1]);
        }
    }

    float* Pp = g_P + (size_t)bc * NN;
    const int i0 = bi * 64 + ty * 4;
    const int j0 = bj * 64 + tx * 4;
    #pragma unroll
    for (int a = 0; a < 4; a++) {
        float4 v = make_float4(c2[a][0].x, c2[a][0].y, c2[a][1].x, c2[a][1].y);
        *(float4*)&Pp[(size_t)(i0 + a) * NDIM + j0] = v;
    }
}

// ---------------------------------------------------------------------------
// K3: per-edge score MLP + gumbel argmax decision, f32x2-packed
// weights packed as float4 pairs -> 2 LDS.128 per h (was 4 LDS.64)
// ---------------------------------------------------------------------------
__device__ __forceinline__ long cum_edges(int i) {
    return (long)i * (2 * NDIM - 1 - i) / 2;
}

__global__ __launch_bounds__(256) void k_mlp(
    const float* __restrict__ sw1, const float* __restrict__ sb1,
    const float* __restrict__ sw2, const float* __restrict__ sb2,
    const float* __restrict__ gumbel, float* __restrict__ out)
{
    __shared__ __align__(16) float4 wab[HDIM];  // (a,a,b,b)
    __shared__ __align__(16) float4 wcd[HDIM];  // (c,c,w,w)
    const int t = threadIdx.x;
    if (t < HDIM) {
        const float a  = sw1[t];
        const float bb = sw1[HDIM + t];
        const float c  = sb1[t];
        const float w  = sw2[t * 2 + 1] - sw2[t * 2];
        wab[t] = make_float4(a, a, bb, bb);
        wcd[t] = make_float4(c, c, w, w);
    }
    __syncthreads();
    const float bd = sb2[1] - sb2[0];

    const long gt = (long)blockIdx.x * 256 + t;

    if (gt < 2 * NDIM) {
        const int b = (int)(gt / NDIM), i = (int)(gt % NDIM);
        out[(size_t)b * NN + (size_t)i * (NDIM + 1)] = 0.0f;
    }

    const long e0 = gt * 8;
    if (e0 >= 2L * EUP) return;
    const int b = (e0 >= EUP);            // EUP % 8 == 0 -> no straddle
    long e = e0 - (long)b * EUP;

    const double dn = 2.0 * NDIM - 1.0;
    int i = (int)((dn - sqrt(dn * dn - 8.0 * (double)e)) * 0.5);
    if (i < 0) i = 0;
    while (cum_edges(i + 1) <= e) i++;
    while (cum_edges(i) > e) i--;
    int j = i + 1 + (int)(e - cum_edges(i));

    const float* P0 = g_P + (size_t)(b * 2 + 0) * NN;
    const float* P1 = g_P + (size_t)(b * 2 + 1) * NN;

    float2 p02[4], p12[4];
    int ii[8], jj[8];
    {
        int ci = i, cj = j;
        float p0s[8], p1s[8];
        #pragma unroll
        for (int k = 0; k < 8; k++) {
            ii[k] = ci; jj[k] = cj;
            const size_t off = (size_t)ci * NDIM + cj;
            p0s[k] = P0[off];
            p1s[k] = P1[off];
            if (++cj == NDIM) { ci++; cj = ci + 1; }
        }
        #pragma unroll
        for (int kp = 0; kp < 4; kp++) {
            p02[kp] = make_float2(p0s[2 * kp], p0s[2 * kp + 1]);
            p12[kp] = make_float2(p1s[2 * kp], p1s[2 * kp + 1]);
        }
    }

    float2 acc2[4];
    #pragma unroll
    for (int kp = 0; kp < 4; kp++) acc2[kp] = make_float2(0.0f, 0.0f);

    #pragma unroll 4
    for (int h = 0; h < HDIM; h++) {
        const float4 qab = wab[h];
        const float4 qcd = wcd[h];
        const float2 a2 = make_float2(qab.x, qab.y);
        const float2 b2 = make_float2(qab.z, qab.w);
        const float2 c2 = make_float2(qcd.x, qcd.y);
        const float2 w2 = make_float2(qcd.z, qcd.w);
        #pragma unroll
        for (int kp = 0; kp < 4; kp++) {
            float2 pre = ffma2(a2, p02[kp], ffma2(b2, p12[kp], c2));
            pre.x = fmaxf(pre.x, 0.0f);
            pre.y = fmaxf(pre.y, 0.0f);
            acc2[kp] = ffma2(w2, pre, acc2[kp]);
        }
    }

    const float* G = gumbel + (size_t)b * NN * 2;
    float* O = out + (size_t)b * NN;
    #pragma unroll
    for (int kp = 0; kp < 4; kp++) {
        #pragma unroll
        for (int half = 0; half < 2; half++) {
            const int k = 2 * kp + half;
            const float accv = half ? acc2[kp].y : acc2[kp].x;
            const float2 g2 = *(const float2*)&G[((size_t)ii[k] * NDIM + jj[k]) * 2];
            const float v = ((accv + bd) + (g2.y - g2.x) > 0.0f) ? 1.0f : 0.0f;
            O[(size_t)ii[k] * NDIM + jj[k]] = v;
            O[(size_t)jj[k] * NDIM + ii[k]] = v;
        }
    }
}

// ---------------------------------------------------------------------------
extern "C" void kernel_launch(void* const* d_in, const int* in_sizes, int n_in,
                              void* d_out, int out_size)
{
    const float* X     = (const float*)d_in[0];
    const float* ef_w1 = (const float*)d_in[1];
    const float* ef_b1 = (const float*)d_in[2];
    const float* ef_w2 = (const float*)d_in[3];
    const float* ef_b2 = (const float*)d_in[4];
    const float* gate  = (const float*)d_in[5];
    const float* sm_w1 = (const float*)d_in[6];
    const float* sm_b1 = (const float*)d_in[7];
    const float* sm_w2 = (const float*)d_in[8];
    const float* sm_b2 = (const float*)d_in[9];
    const float* gumb  = (const float*)d_in[10];
    float* out = (float*)d_out;

    k_prep<<<384, 256>>>(X, ef_w1, ef_b1, ef_w2, ef_b2, gate);
    k_gram<<<dim3(78, 4), 256>>>();
    const int nthreads = (2 * EUP) / 8;               // 73632
    const int nblocks  = (nthreads + 255) / 256;      // 288
    k_mlp<<<nblocks, 256>>>(sm_w1, sm_b1, sm_w2, sm_b2, gumb, out);
}